// round 5
// baseline (speedup 1.0000x reference)
#include <cuda_runtime.h>

#define MAXN 100000
#define MAXE 1000000
#define DIM 64

// ---------------- scratch (device globals; no allocation allowed) ----------------
__device__ int   g_deg[MAXN];        // edge count per dst (memset 0; deg = count+1)
__device__ float g_dinv[MAXN];
__device__ int   g_off[MAXN + 1];
__device__ int   g_cur[MAXN];
__device__ int   g_srcs[MAXE];
__device__ float g_xs[MAXN * DIM];   // dinv[i] * x[i]
__device__ float g_y[MAXN * DIM];    // aggregated features
__device__ float g_stats[2 * DIM];   // [0:64) col sums, [64:128) col sumsq

// ---------------- 1. degree histogram over dst (4 edges / thread) ----------------
__global__ void k_hist(const int4* __restrict__ dst4, int E4, const int* __restrict__ dst, int rem_base, int E) {
    int i = blockIdx.x * blockDim.x + threadIdx.x;
    if (i < E4) {
        int4 d = dst4[i];
        atomicAdd(&g_deg[d.x], 1);
        atomicAdd(&g_deg[d.y], 1);
        atomicAdd(&g_deg[d.z], 1);
        atomicAdd(&g_deg[d.w], 1);
    }
    int r = rem_base + i;
    if (i < 4 && r < E) atomicAdd(&g_deg[dst[r]], 1);
}

// ---------------- 2. xs = dinv * x (2 x float4 per thread; emits g_dinv) ----------
__global__ void k_xs(const float4* __restrict__ x4, int n) {
    int i = (blockIdx.x * blockDim.x + threadIdx.x) * 2;
    if (i < n * 16) {
        int node = i >> 4;
        float dv = rsqrtf((float)(g_deg[node] + 1));   // +1 self loop
        float4 a = x4[i], c = x4[i + 1];
        a.x *= dv; a.y *= dv; a.z *= dv; a.w *= dv;
        c.x *= dv; c.y *= dv; c.z *= dv; c.w *= dv;
        ((float4*)g_xs)[i]     = a;
        ((float4*)g_xs)[i + 1] = c;
        if ((i & 15) == 0) g_dinv[node] = dv;
    }
}

// ---------------- 3. exclusive scan of edge counts -> offsets (warp-shfl) --------
__global__ void k_scan(int n) {
    __shared__ int warppre[32];
    __shared__ int s_run, s_tot;
    int tid = threadIdx.x, lane = tid & 31, wid = tid >> 5;
    if (tid == 0) s_run = 0;
    if (tid < 128) g_stats[tid] = 0.f;     // fold stats zeroing in here
    __syncthreads();
    int nchunk = (n + 4095) >> 12;
    for (int c = 0; c < nchunk; c++) {
        int base = (c << 12) + tid * 4;
        int v0 = (base     < n) ? g_deg[base]     : 0;
        int v1 = (base + 1 < n) ? g_deg[base + 1] : 0;
        int v2 = (base + 2 < n) ? g_deg[base + 2] : 0;
        int v3 = (base + 3 < n) ? g_deg[base + 3] : 0;
        int t = v0 + v1 + v2 + v3;
        int s = t;
#pragma unroll
        for (int o = 1; o < 32; o <<= 1) {
            int u = __shfl_up_sync(0xffffffffu, s, o);
            if (lane >= o) s += u;
        }
        if (lane == 31) warppre[wid] = s;
        __syncthreads();
        if (wid == 0) {
            int w = warppre[lane];
            int ws = w;
#pragma unroll
            for (int o = 1; o < 32; o <<= 1) {
                int u = __shfl_up_sync(0xffffffffu, ws, o);
                if (lane >= o) ws += u;
            }
            warppre[lane] = ws - w;          // exclusive warp prefix
            if (lane == 31) s_tot = ws;      // chunk total
        }
        __syncthreads();
        int excl = s_run + warppre[wid] + (s - t);
        if (base     < n) { g_off[base]     = excl; g_cur[base]     = excl; } excl += v0;
        if (base + 1 < n) { g_off[base + 1] = excl; g_cur[base + 1] = excl; } excl += v1;
        if (base + 2 < n) { g_off[base + 2] = excl; g_cur[base + 2] = excl; } excl += v2;
        if (base + 3 < n) { g_off[base + 3] = excl; g_cur[base + 3] = excl; }
        __syncthreads();
        if (tid == 0) s_run += s_tot;
        __syncthreads();
    }
    if (tid == 0) g_off[n] = s_run;
}

// ---------------- 4. CSR fill (4 edges / thread) ----------------
__global__ void k_fill(const int4* __restrict__ src4, const int4* __restrict__ dst4, int E4,
                       const int* __restrict__ src, const int* __restrict__ dst, int rem_base, int E) {
    int i = blockIdx.x * blockDim.x + threadIdx.x;
    if (i < E4) {
        int4 d = dst4[i];
        int4 s = src4[i];
        int p0 = atomicAdd(&g_cur[d.x], 1);
        int p1 = atomicAdd(&g_cur[d.y], 1);
        int p2 = atomicAdd(&g_cur[d.z], 1);
        int p3 = atomicAdd(&g_cur[d.w], 1);
        g_srcs[p0] = s.x;
        g_srcs[p1] = s.y;
        g_srcs[p2] = s.z;
        g_srcs[p3] = s.w;
    }
    int r = rem_base + i;
    if (i < 4 && r < E) {
        int p = atomicAdd(&g_cur[dst[r]], 1);
        g_srcs[p] = src[r];
    }
}

// ---------------- 5. aggregation: one warp per node, float2 per lane ----------------
__global__ void __launch_bounds__(256) k_agg(int n) {
    int warp = (blockIdx.x * blockDim.x + threadIdx.x) >> 5;
    int lane = threadIdx.x & 31;
    if (warp >= n) return;
    const float2* xs2 = (const float2*)g_xs;
    int s0 = g_off[warp], s1 = g_off[warp + 1];
    float2 a0 = xs2[warp * 32 + lane];   // self-loop: dinv[dst]*x[dst]
    float2 a1 = make_float2(0.f, 0.f);
    float2 a2 = make_float2(0.f, 0.f);
    float2 a3 = make_float2(0.f, 0.f);
    int e = s0;
    for (; e + 4 <= s1; e += 4) {
        int i0 = g_srcs[e], i1 = g_srcs[e + 1], i2 = g_srcs[e + 2], i3 = g_srcs[e + 3];
        float2 v0 = xs2[i0 * 32 + lane];
        float2 v1 = xs2[i1 * 32 + lane];
        float2 v2 = xs2[i2 * 32 + lane];
        float2 v3 = xs2[i3 * 32 + lane];
        a0.x += v0.x; a0.y += v0.y;
        a1.x += v1.x; a1.y += v1.y;
        a2.x += v2.x; a2.y += v2.y;
        a3.x += v3.x; a3.y += v3.y;
    }
    for (; e < s1; e++) {
        int i0 = g_srcs[e];
        float2 v = xs2[i0 * 32 + lane];
        a0.x += v.x; a0.y += v.y;
    }
    float dv = g_dinv[warp];
    float2 o;
    o.x = (a0.x + a1.x + a2.x + a3.x) * dv;
    o.y = (a0.y + a1.y + a2.y + a3.y) * dv;
    ((float2*)g_y)[warp * 32 + lane] = o;
}

// ---------------- 6. GEMM (y @ W + b), ReLU, store, accumulate BN stats ----------
__global__ void __launch_bounds__(256) k_gemm(const float* __restrict__ W,
                                              const float* __restrict__ b,
                                              float* __restrict__ out, int n) {
    __shared__ float sW[64 * 64];
    __shared__ float sY[64 * 68];   // stride 68 -> conflict-free, float4-aligned
    __shared__ float sB[64];
    __shared__ float sSum[128];
    int tid = threadIdx.x, lane = tid & 31;

    for (int i = tid; i < 4096; i += 256) sW[i] = W[i];
    if (tid < 64) sB[tid] = b[tid];
    if (tid < 128) sSum[tid] = 0.f;

    int row0 = blockIdx.x * 64;
    const float4* y4 = (const float4*)g_y;
    for (int i = tid; i < 64 * 16; i += 256) {
        int r = i >> 4, q = i & 15;
        int grow = row0 + r;
        float4 v = (grow < n) ? y4[grow * 16 + q] : make_float4(0.f, 0.f, 0.f, 0.f);
        ((float4*)(sY + r * 68))[q] = v;
    }
    __syncthreads();

    int r  = tid >> 2;          // 0..63 (row within tile)
    int cg = (tid & 3) << 4;    // 0,16,32,48 (col base)
    float acc[16];
#pragma unroll
    for (int j = 0; j < 16; j++) acc[j] = 0.f;
    const float* yrow = sY + r * 68;
#pragma unroll
    for (int k = 0; k < 64; k++) {
        float yk = yrow[k];
        const float4* wr = (const float4*)(sW + k * 64 + cg);
#pragma unroll
        for (int q = 0; q < 4; q++) {
            float4 w = wr[q];
            acc[q * 4 + 0] = fmaf(yk, w.x, acc[q * 4 + 0]);
            acc[q * 4 + 1] = fmaf(yk, w.y, acc[q * 4 + 1]);
            acc[q * 4 + 2] = fmaf(yk, w.z, acc[q * 4 + 2]);
            acc[q * 4 + 3] = fmaf(yk, w.w, acc[q * 4 + 3]);
        }
    }
    int grow = row0 + r;
#pragma unroll
    for (int j = 0; j < 16; j++) {
        float v = acc[j] + sB[cg + j];
        acc[j] = fmaxf(v, 0.f);
    }
    if (grow < n) {
        float4* o4 = (float4*)(out + grow * 64 + cg);
        o4[0] = make_float4(acc[0],  acc[1],  acc[2],  acc[3]);
        o4[1] = make_float4(acc[4],  acc[5],  acc[6],  acc[7]);
        o4[2] = make_float4(acc[8],  acc[9],  acc[10], acc[11]);
        o4[3] = make_float4(acc[12], acc[13], acc[14], acc[15]);
    } else {
#pragma unroll
        for (int j = 0; j < 16; j++) acc[j] = 0.f;   // don't pollute stats
    }
    // reduce over the 8 rows held by this warp (lanes differing in bits 2..4)
    float sq[16];
#pragma unroll
    for (int j = 0; j < 16; j++) sq[j] = acc[j] * acc[j];
#pragma unroll
    for (int off = 4; off < 32; off <<= 1) {
#pragma unroll
        for (int j = 0; j < 16; j++) {
            acc[j] += __shfl_xor_sync(0xffffffffu, acc[j], off);
            sq[j]  += __shfl_xor_sync(0xffffffffu, sq[j],  off);
        }
    }
    if (lane < 4) {
#pragma unroll
        for (int j = 0; j < 16; j++) {
            atomicAdd(&sSum[cg + j],      acc[j]);
            atomicAdd(&sSum[64 + cg + j], sq[j]);
        }
    }
    __syncthreads();
    if (tid < 128) atomicAdd(&g_stats[tid], sSum[tid]);
}

// ---------------- 7. fused BN stats + apply (in place on out) ----------------
__global__ void k_bn(float4* __restrict__ out,
                     const float* __restrict__ gamma,
                     const float* __restrict__ beta, int n) {
    __shared__ float ssc[64], ssh[64];
    int tid = threadIdx.x;
    if (tid < 64) {
        float inv_n = 1.0f / (float)n;
        float mean = g_stats[tid] * inv_n;
        float var  = fmaxf(g_stats[64 + tid] * inv_n - mean * mean, 0.f);
        float sc = gamma[tid] * rsqrtf(var + 1e-5f);
        ssc[tid] = sc;
        ssh[tid] = beta[tid] - mean * sc;
    }
    __syncthreads();
    int i = blockIdx.x * blockDim.x + tid;
    if (i < n * 16) {
        float4 v  = out[i];
        float4 sc = ((const float4*)ssc)[i & 15];
        float4 sh = ((const float4*)ssh)[i & 15];
        v.x = fmaf(v.x, sc.x, sh.x);
        v.y = fmaf(v.y, sc.y, sh.y);
        v.z = fmaf(v.z, sc.z, sh.z);
        v.w = fmaf(v.w, sc.w, sh.w);
        out[i] = v;
    }
}

extern "C" void kernel_launch(void* const* d_in, const int* in_sizes, int n_in,
                              void* d_out, int out_size) {
    const float* x     = (const float*)d_in[0];
    const int*   ei    = (const int*)d_in[1];
    const float* W     = (const float*)d_in[2];
    const float* b     = (const float*)d_in[3];
    const float* gamma = (const float*)d_in[4];
    const float* beta  = (const float*)d_in[5];
    float* out = (float*)d_out;

    int N = in_sizes[0] / DIM;
    int E = in_sizes[1] / 2;
    const int* src = ei;
    const int* dst = ei + E;
    int E4 = E / 4;
    int rem = E4 * 4;

    void* p_deg = nullptr;
    cudaGetSymbolAddress(&p_deg, g_deg);
    cudaMemsetAsync(p_deg, 0, (size_t)N * sizeof(int));

    k_hist<<<(E4 + 255) / 256, 256>>>((const int4*)dst, E4, dst, rem, E);
    k_xs<<<(N * 8 + 255) / 256, 256>>>((const float4*)x, N);
    k_scan<<<1, 1024>>>(N);
    k_fill<<<(E4 + 255) / 256, 256>>>((const int4*)src, (const int4*)dst, E4, src, dst, rem, E);
    k_agg<<<(N + 7) / 8, 256>>>(N);
    k_gemm<<<(N + 63) / 64, 256>>>(W, b, out, N);
    k_bn<<<(N * 16 + 255) / 256, 256>>>((float4*)out, gamma, beta, N);
}

// round 6
// speedup vs baseline: 1.3007x; 1.3007x over previous
#include <cuda_runtime.h>
#include <cuda_fp16.h>

#define MAXN 100000
#define MAXE 1000000
#define DIM 64

// ---------------- scratch (device globals; no allocation allowed) ----------------
__device__ int     g_deg[MAXN];        // edge count per dst (memset 0; deg = count+1)
__device__ float   g_dinv[MAXN];
__device__ int     g_off[MAXN + 1];
__device__ int     g_cur[MAXN];
__device__ int     g_srcs[MAXE];
__device__ __half2 g_xsh[MAXN * 32];   // fp16 dinv[i]*x[i], 32 half2 per node
__device__ float   g_y[MAXN * DIM];    // aggregated features (fp32)
__device__ float   g_stats[2 * DIM];   // [0:64) col sums, [64:128) col sumsq

// ---------------- 1. degree histogram over dst ----------------
__global__ void k_hist(const int* __restrict__ dst, int E) {
    int e = blockIdx.x * blockDim.x + threadIdx.x;
    if (e < E) atomicAdd(&g_deg[dst[e]], 1);
}

// ---------------- 2. xs = fp16(dinv * x), 8 floats / thread; emits g_dinv -------
__global__ void k_xs(const float4* __restrict__ x4, int n) {
    int i = blockIdx.x * blockDim.x + threadIdx.x;   // 8 floats per thread
    if (i < n * 8) {
        int node = i >> 3;
        float dv = rsqrtf((float)(g_deg[node] + 1));  // +1 self loop
        float4 a = x4[2 * i], c = x4[2 * i + 1];
        __half2 h[4];
        h[0] = __floats2half2_rn(a.x * dv, a.y * dv);
        h[1] = __floats2half2_rn(a.z * dv, a.w * dv);
        h[2] = __floats2half2_rn(c.x * dv, c.y * dv);
        h[3] = __floats2half2_rn(c.z * dv, c.w * dv);
        *(uint4*)&g_xsh[i * 4] = *(uint4*)h;          // one 16B store
        if ((i & 7) == 0) g_dinv[node] = dv;
    }
}

// ---------------- 3. exclusive scan of edge counts -> offsets (warp-shfl) --------
__global__ void k_scan(int n) {
    __shared__ int warppre[32];
    __shared__ int s_run, s_tot;
    int tid = threadIdx.x, lane = tid & 31, wid = tid >> 5;
    if (tid == 0) s_run = 0;
    if (tid < 128) g_stats[tid] = 0.f;     // fold stats zeroing in here
    __syncthreads();
    int nchunk = (n + 4095) >> 12;
    for (int c = 0; c < nchunk; c++) {
        int base = (c << 12) + tid * 4;
        int v0 = (base     < n) ? g_deg[base]     : 0;
        int v1 = (base + 1 < n) ? g_deg[base + 1] : 0;
        int v2 = (base + 2 < n) ? g_deg[base + 2] : 0;
        int v3 = (base + 3 < n) ? g_deg[base + 3] : 0;
        int t = v0 + v1 + v2 + v3;
        int s = t;
#pragma unroll
        for (int o = 1; o < 32; o <<= 1) {
            int u = __shfl_up_sync(0xffffffffu, s, o);
            if (lane >= o) s += u;
        }
        if (lane == 31) warppre[wid] = s;
        __syncthreads();
        if (wid == 0) {
            int w = warppre[lane];
            int ws = w;
#pragma unroll
            for (int o = 1; o < 32; o <<= 1) {
                int u = __shfl_up_sync(0xffffffffu, ws, o);
                if (lane >= o) ws += u;
            }
            warppre[lane] = ws - w;          // exclusive warp prefix
            if (lane == 31) s_tot = ws;      // chunk total
        }
        __syncthreads();
        int excl = s_run + warppre[wid] + (s - t);
        if (base     < n) { g_off[base]     = excl; g_cur[base]     = excl; } excl += v0;
        if (base + 1 < n) { g_off[base + 1] = excl; g_cur[base + 1] = excl; } excl += v1;
        if (base + 2 < n) { g_off[base + 2] = excl; g_cur[base + 2] = excl; } excl += v2;
        if (base + 3 < n) { g_off[base + 3] = excl; g_cur[base + 3] = excl; }
        __syncthreads();
        if (tid == 0) s_run += s_tot;
        __syncthreads();
    }
    if (tid == 0) g_off[n] = s_run;
}

// ---------------- 4. CSR fill ----------------
__global__ void k_fill(const int* __restrict__ src, const int* __restrict__ dst, int E) {
    int e = blockIdx.x * blockDim.x + threadIdx.x;
    if (e < E) {
        int d = dst[e];
        int p = atomicAdd(&g_cur[d], 1);
        g_srcs[p] = src[e];
    }
}

// ---------------- 5. aggregation: one warp per node, half2 gather, fp32 accum ----
__global__ void __launch_bounds__(256) k_agg(int n) {
    int warp = (blockIdx.x * blockDim.x + threadIdx.x) >> 5;
    int lane = threadIdx.x & 31;
    if (warp >= n) return;
    const __half2* xs = g_xsh;
    int s0 = g_off[warp], s1 = g_off[warp + 1];
    float2 a0 = __half22float2(xs[warp * 32 + lane]);   // self-loop: dinv[dst]*x[dst]
    float2 a1 = make_float2(0.f, 0.f);
    float2 a2 = make_float2(0.f, 0.f);
    float2 a3 = make_float2(0.f, 0.f);
    int e = s0;
    for (; e + 4 <= s1; e += 4) {
        int i0 = g_srcs[e], i1 = g_srcs[e + 1], i2 = g_srcs[e + 2], i3 = g_srcs[e + 3];
        float2 v0 = __half22float2(xs[i0 * 32 + lane]);
        float2 v1 = __half22float2(xs[i1 * 32 + lane]);
        float2 v2 = __half22float2(xs[i2 * 32 + lane]);
        float2 v3 = __half22float2(xs[i3 * 32 + lane]);
        a0.x += v0.x; a0.y += v0.y;
        a1.x += v1.x; a1.y += v1.y;
        a2.x += v2.x; a2.y += v2.y;
        a3.x += v3.x; a3.y += v3.y;
    }
    for (; e < s1; e++) {
        float2 v = __half22float2(xs[g_srcs[e] * 32 + lane]);
        a0.x += v.x; a0.y += v.y;
    }
    float dv = g_dinv[warp];
    float2 o;
    o.x = (a0.x + a1.x + a2.x + a3.x) * dv;
    o.y = (a0.y + a1.y + a2.y + a3.y) * dv;
    ((float2*)g_y)[warp * 32 + lane] = o;
}

// ---------------- 6. GEMM 128-row tile (y @ W + b), ReLU, store, BN stats -------
__global__ void __launch_bounds__(256) k_gemm(const float* __restrict__ W,
                                              const float* __restrict__ b,
                                              float* __restrict__ out, int n) {
    extern __shared__ float smem[];
    float* sW   = smem;                 // 4096
    float* sY   = smem + 4096;          // 128*68 = 8704
    float* sB   = sY + 128 * 68;        // 64
    float* sSum = sB + 64;              // 128
    int tid = threadIdx.x, lane = tid & 31;

    for (int i = tid; i < 4096; i += 256) sW[i] = W[i];
    if (tid < 64) sB[tid] = b[tid];
    if (tid < 128) sSum[tid] = 0.f;

    int row0 = blockIdx.x * 128;
    const float4* y4 = (const float4*)g_y;
    for (int i = tid; i < 128 * 16; i += 256) {
        int r = i >> 4, q = i & 15;
        int grow = row0 + r;
        float4 v = (grow < n) ? y4[grow * 16 + q] : make_float4(0.f, 0.f, 0.f, 0.f);
        ((float4*)(sY + r * 68))[q] = v;
    }
    __syncthreads();

    int r  = tid >> 2;          // 0..63; this thread handles rows r and r+64
    int cg = (tid & 3) << 4;    // 0,16,32,48 (col base)
    float acc[32];
#pragma unroll
    for (int j = 0; j < 32; j++) acc[j] = 0.f;
    const float* y0 = sY + r * 68;
    const float* y1 = sY + (r + 64) * 68;
#pragma unroll
    for (int k = 0; k < 64; k++) {
        float yk0 = y0[k];
        float yk1 = y1[k];
        const float4* wr = (const float4*)(sW + k * 64 + cg);
#pragma unroll
        for (int q = 0; q < 4; q++) {
            float4 w = wr[q];
            acc[q * 4 + 0]      = fmaf(yk0, w.x, acc[q * 4 + 0]);
            acc[q * 4 + 1]      = fmaf(yk0, w.y, acc[q * 4 + 1]);
            acc[q * 4 + 2]      = fmaf(yk0, w.z, acc[q * 4 + 2]);
            acc[q * 4 + 3]      = fmaf(yk0, w.w, acc[q * 4 + 3]);
            acc[16 + q * 4 + 0] = fmaf(yk1, w.x, acc[16 + q * 4 + 0]);
            acc[16 + q * 4 + 1] = fmaf(yk1, w.y, acc[16 + q * 4 + 1]);
            acc[16 + q * 4 + 2] = fmaf(yk1, w.z, acc[16 + q * 4 + 2]);
            acc[16 + q * 4 + 3] = fmaf(yk1, w.w, acc[16 + q * 4 + 3]);
        }
    }
    int grow0 = row0 + r;
    int grow1 = row0 + 64 + r;
#pragma unroll
    for (int j = 0; j < 16; j++) {
        acc[j]      = fmaxf(acc[j]      + sB[cg + j], 0.f);
        acc[16 + j] = fmaxf(acc[16 + j] + sB[cg + j], 0.f);
    }
    if (grow0 < n) {
        float4* o4 = (float4*)(out + grow0 * 64 + cg);
        o4[0] = make_float4(acc[0],  acc[1],  acc[2],  acc[3]);
        o4[1] = make_float4(acc[4],  acc[5],  acc[6],  acc[7]);
        o4[2] = make_float4(acc[8],  acc[9],  acc[10], acc[11]);
        o4[3] = make_float4(acc[12], acc[13], acc[14], acc[15]);
    } else {
#pragma unroll
        for (int j = 0; j < 16; j++) acc[j] = 0.f;
    }
    if (grow1 < n) {
        float4* o4 = (float4*)(out + grow1 * 64 + cg);
        o4[0] = make_float4(acc[16], acc[17], acc[18], acc[19]);
        o4[1] = make_float4(acc[20], acc[21], acc[22], acc[23]);
        o4[2] = make_float4(acc[24], acc[25], acc[26], acc[27]);
        o4[3] = make_float4(acc[28], acc[29], acc[30], acc[31]);
    } else {
#pragma unroll
        for (int j = 0; j < 16; j++) acc[16 + j] = 0.f;
    }
    // BN partial stats: combine both rows, reduce over the 8 r-values in the warp
    float s[16], sq[16];
#pragma unroll
    for (int j = 0; j < 16; j++) {
        s[j]  = acc[j] + acc[16 + j];
        sq[j] = acc[j] * acc[j] + acc[16 + j] * acc[16 + j];
    }
#pragma unroll
    for (int off = 4; off < 32; off <<= 1) {
#pragma unroll
        for (int j = 0; j < 16; j++) {
            s[j]  += __shfl_xor_sync(0xffffffffu, s[j],  off);
            sq[j] += __shfl_xor_sync(0xffffffffu, sq[j], off);
        }
    }
    if (lane < 4) {
#pragma unroll
        for (int j = 0; j < 16; j++) {
            atomicAdd(&sSum[cg + j],      s[j]);
            atomicAdd(&sSum[64 + cg + j], sq[j]);
        }
    }
    __syncthreads();
    if (tid < 128) atomicAdd(&g_stats[tid], sSum[tid]);
}

// ---------------- 7. fused BN stats + apply (in place on out) ----------------
__global__ void k_bn(float4* __restrict__ out,
                     const float* __restrict__ gamma,
                     const float* __restrict__ beta, int n) {
    __shared__ float ssc[64], ssh[64];
    int tid = threadIdx.x;
    if (tid < 64) {
        float inv_n = 1.0f / (float)n;
        float mean = g_stats[tid] * inv_n;
        float var  = fmaxf(g_stats[64 + tid] * inv_n - mean * mean, 0.f);
        float sc = gamma[tid] * rsqrtf(var + 1e-5f);
        ssc[tid] = sc;
        ssh[tid] = beta[tid] - mean * sc;
    }
    __syncthreads();
    int i = blockIdx.x * blockDim.x + tid;
    if (i < n * 16) {
        float4 v  = out[i];
        float4 sc = ((const float4*)ssc)[i & 15];
        float4 sh = ((const float4*)ssh)[i & 15];
        v.x = fmaf(v.x, sc.x, sh.x);
        v.y = fmaf(v.y, sc.y, sh.y);
        v.z = fmaf(v.z, sc.z, sh.z);
        v.w = fmaf(v.w, sc.w, sh.w);
        out[i] = v;
    }
}

extern "C" void kernel_launch(void* const* d_in, const int* in_sizes, int n_in,
                              void* d_out, int out_size) {
    const float* x     = (const float*)d_in[0];
    const int*   ei    = (const int*)d_in[1];
    const float* W     = (const float*)d_in[2];
    const float* b     = (const float*)d_in[3];
    const float* gamma = (const float*)d_in[4];
    const float* beta  = (const float*)d_in[5];
    float* out = (float*)d_out;

    int N = in_sizes[0] / DIM;
    int E = in_sizes[1] / 2;
    const int* src = ei;
    const int* dst = ei + E;

    void* p_deg = nullptr;
    cudaGetSymbolAddress(&p_deg, g_deg);
    cudaMemsetAsync(p_deg, 0, (size_t)N * sizeof(int));

    const int GEMM_SMEM = (4096 + 128 * 68 + 64 + 128) * (int)sizeof(float);
    cudaFuncSetAttribute(k_gemm, cudaFuncAttributeMaxDynamicSharedMemorySize, GEMM_SMEM);

    k_hist<<<(E + 255) / 256, 256>>>(dst, E);
    k_xs<<<(N * 8 + 255) / 256, 256>>>((const float4*)x, N);
    k_scan<<<1, 1024>>>(N);
    k_fill<<<(E + 255) / 256, 256>>>(src, dst, E);
    k_agg<<<(N + 7) / 8, 256>>>(N);
    k_gemm<<<(N + 127) / 128, 256, GEMM_SMEM>>>(W, b, out, N);
    k_bn<<<(N * 16 + 255) / 256, 256>>>((float4*)out, gamma, beta, N);
}

// round 8
// speedup vs baseline: 1.3123x; 1.0089x over previous
#include <cuda_runtime.h>
#include <cuda_fp16.h>

#define MAXN 100000
#define MAXE 1000000
#define DIM 64

// ---------------- scratch (device globals; no allocation allowed) ----------------
__device__ int     g_deg[MAXN];        // edge count per dst (memset 0; deg = count+1)
__device__ float   g_dinv[MAXN];
__device__ int     g_off[MAXN + 1];
__device__ int     g_cur[MAXN];
__device__ int     g_srcs[MAXE];
__device__ __half2 g_xsh[MAXN * 32];   // fp16 dinv[i]*x[i], 32 half2 per node
__device__ float   g_y[MAXN * DIM];    // aggregated features (fp32)
__device__ float   g_stats[2 * DIM];   // [0:64) col sums, [64:128) col sumsq

// ---------------- 1. degree histogram over dst ----------------
__global__ void k_hist(const int* __restrict__ dst, int E) {
    int e = blockIdx.x * blockDim.x + threadIdx.x;
    if (e < E) atomicAdd(&g_deg[dst[e]], 1);
}

// ---------------- 2. combined: block 0 = scan, blocks 1.. = xs ----------------
__global__ void __launch_bounds__(1024) k_prep(const float4* __restrict__ x4, int n) {
    int tid = threadIdx.x, lane = tid & 31, wid = tid >> 5;
    if (blockIdx.x != 0) {
        // ---- xs = fp16(dinv * x), 8 floats / thread; emits g_dinv ----
        int i = (blockIdx.x - 1) * 1024 + tid;
        if (i < n * 8) {
            int node = i >> 3;
            float dv = rsqrtf((float)(g_deg[node] + 1));  // +1 self loop
            float4 a = x4[2 * i], c = x4[2 * i + 1];
            __half2 h[4];
            h[0] = __floats2half2_rn(a.x * dv, a.y * dv);
            h[1] = __floats2half2_rn(a.z * dv, a.w * dv);
            h[2] = __floats2half2_rn(c.x * dv, c.y * dv);
            h[3] = __floats2half2_rn(c.z * dv, c.w * dv);
            *(uint4*)&g_xsh[i * 4] = *(uint4*)h;          // one 16B store
            if ((i & 7) == 0) g_dinv[node] = dv;
        }
        return;
    }
    // ---- exclusive scan of edge counts -> offsets (warp-shfl) ----
    __shared__ int warppre[32];
    __shared__ int s_run, s_tot;
    if (tid == 0) s_run = 0;
    if (tid < 128) g_stats[tid] = 0.f;     // fold stats zeroing in here
    __syncthreads();
    int nchunk = (n + 4095) >> 12;
    for (int c = 0; c < nchunk; c++) {
        int base = (c << 12) + tid * 4;
        int v0 = (base     < n) ? g_deg[base]     : 0;
        int v1 = (base + 1 < n) ? g_deg[base + 1] : 0;
        int v2 = (base + 2 < n) ? g_deg[base + 2] : 0;
        int v3 = (base + 3 < n) ? g_deg[base + 3] : 0;
        int t = v0 + v1 + v2 + v3;
        int s = t;
#pragma unroll
        for (int o = 1; o < 32; o <<= 1) {
            int u = __shfl_up_sync(0xffffffffu, s, o);
            if (lane >= o) s += u;
        }
        if (lane == 31) warppre[wid] = s;
        __syncthreads();
        if (wid == 0) {
            int w = warppre[lane];
            int ws = w;
#pragma unroll
            for (int o = 1; o < 32; o <<= 1) {
                int u = __shfl_up_sync(0xffffffffu, ws, o);
                if (lane >= o) ws += u;
            }
            warppre[lane] = ws - w;          // exclusive warp prefix
            if (lane == 31) s_tot = ws;      // chunk total
        }
        __syncthreads();
        int excl = s_run + warppre[wid] + (s - t);
        if (base     < n) { g_off[base]     = excl; g_cur[base]     = excl; } excl += v0;
        if (base + 1 < n) { g_off[base + 1] = excl; g_cur[base + 1] = excl; } excl += v1;
        if (base + 2 < n) { g_off[base + 2] = excl; g_cur[base + 2] = excl; } excl += v2;
        if (base + 3 < n) { g_off[base + 3] = excl; g_cur[base + 3] = excl; }
        __syncthreads();
        if (tid == 0) s_run += s_tot;
        __syncthreads();
    }
    if (tid == 0) g_off[n] = s_run;
}

// ---------------- 3. CSR fill ----------------
__global__ void k_fill(const int* __restrict__ src, const int* __restrict__ dst, int E) {
    int e = blockIdx.x * blockDim.x + threadIdx.x;
    if (e < E) {
        int d = dst[e];
        int p = atomicAdd(&g_cur[d], 1);
        g_srcs[p] = src[e];
    }
}

// ---------------- 4. aggregation: one warp per node, 2 edges per warp-load -------
// Half-warp h (lanes 0-15 / 16-31) handles even/odd edge of each pair; each lane
// loads 8B (4 halves = cols [sl*4, sl*4+4)). 8 edges (1KB) in flight per warp.
__global__ void __launch_bounds__(256) k_agg(int n) {
    int warp = (blockIdx.x * blockDim.x + threadIdx.x) >> 5;
    int lane = threadIdx.x & 31;
    if (warp >= n) return;
    int h  = lane >> 4;        // 0 = even edge of pair, 1 = odd edge
    int sl = lane & 15;        // uint2 column index within row
    const uint2* xs = (const uint2*)g_xsh;   // 16 uint2 per node row (128B)

    int s0 = g_off[warp], s1 = g_off[warp + 1];
    float4 a0 = make_float4(0.f, 0.f, 0.f, 0.f);
    float4 a1 = a0, a2 = a0, a3 = a0;
    if (h == 0) {              // self-loop term once
        uint2 sv = xs[warp * 16 + sl];
        float2 lo = __half22float2(*(__half2*)&sv.x);
        float2 hi = __half22float2(*(__half2*)&sv.y);
        a0 = make_float4(lo.x, lo.y, hi.x, hi.y);
    }
    int e = s0;
    for (; e + 8 <= s1; e += 8) {
        int i0 = g_srcs[e + 0 + h];
        int i1 = g_srcs[e + 2 + h];
        int i2 = g_srcs[e + 4 + h];
        int i3 = g_srcs[e + 6 + h];
        uint2 v0 = xs[i0 * 16 + sl];
        uint2 v1 = xs[i1 * 16 + sl];
        uint2 v2 = xs[i2 * 16 + sl];
        uint2 v3 = xs[i3 * 16 + sl];
        float2 l0 = __half22float2(*(__half2*)&v0.x), h0 = __half22float2(*(__half2*)&v0.y);
        float2 l1 = __half22float2(*(__half2*)&v1.x), h1 = __half22float2(*(__half2*)&v1.y);
        float2 l2 = __half22float2(*(__half2*)&v2.x), h2 = __half22float2(*(__half2*)&v2.y);
        float2 l3 = __half22float2(*(__half2*)&v3.x), h3 = __half22float2(*(__half2*)&v3.y);
        a0.x += l0.x; a0.y += l0.y; a0.z += h0.x; a0.w += h0.y;
        a1.x += l1.x; a1.y += l1.y; a1.z += h1.x; a1.w += h1.y;
        a2.x += l2.x; a2.y += l2.y; a2.z += h2.x; a2.w += h2.y;
        a3.x += l3.x; a3.y += l3.y; a3.z += h3.x; a3.w += h3.y;
    }
    for (; e + 2 <= s1; e += 2) {           // leftover pairs
        int i0 = g_srcs[e + h];
        uint2 v = xs[i0 * 16 + sl];
        float2 lo = __half22float2(*(__half2*)&v.x);
        float2 hi = __half22float2(*(__half2*)&v.y);
        a0.x += lo.x; a0.y += lo.y; a0.z += hi.x; a0.w += hi.y;
    }
    if (e < s1 && h == 0) {                 // odd single edge
        uint2 v = xs[g_srcs[e] * 16 + sl];
        float2 lo = __half22float2(*(__half2*)&v.x);
        float2 hi = __half22float2(*(__half2*)&v.y);
        a0.x += lo.x; a0.y += lo.y; a0.z += hi.x; a0.w += hi.y;
    }
    float4 a;
    a.x = a0.x + a1.x + a2.x + a3.x;
    a.y = a0.y + a1.y + a2.y + a3.y;
    a.z = a0.z + a1.z + a2.z + a3.z;
    a.w = a0.w + a1.w + a2.w + a3.w;
    // merge odd-edge half-warp into even-edge half-warp
    a.x += __shfl_xor_sync(0xffffffffu, a.x, 16);
    a.y += __shfl_xor_sync(0xffffffffu, a.y, 16);
    a.z += __shfl_xor_sync(0xffffffffu, a.z, 16);
    a.w += __shfl_xor_sync(0xffffffffu, a.w, 16);
    if (h == 0) {
        float dv = g_dinv[warp];
        a.x *= dv; a.y *= dv; a.z *= dv; a.w *= dv;
        ((float4*)(g_y + warp * 64))[sl] = a;
    }
}

// ---------------- 5. GEMM 128-row tile (y @ W + b), ReLU, store, BN stats -------
__global__ void __launch_bounds__(256) k_gemm(const float* __restrict__ W,
                                              const float* __restrict__ b,
                                              float* __restrict__ out, int n) {
    extern __shared__ float smem[];
    float* sW   = smem;                 // 4096
    float* sY   = smem + 4096;          // 128*68 = 8704
    float* sB   = sY + 128 * 68;        // 64
    float* sSum = sB + 64;              // 128
    int tid = threadIdx.x, lane = tid & 31;

    for (int i = tid; i < 4096; i += 256) sW[i] = W[i];
    if (tid < 64) sB[tid] = b[tid];
    if (tid < 128) sSum[tid] = 0.f;

    int row0 = blockIdx.x * 128;
    const float4* y4 = (const float4*)g_y;
    for (int i = tid; i < 128 * 16; i += 256) {
        int r = i >> 4, q = i & 15;
        int grow = row0 + r;
        float4 v = (grow < n) ? y4[grow * 16 + q] : make_float4(0.f, 0.f, 0.f, 0.f);
        ((float4*)(sY + r * 68))[q] = v;
    }
    __syncthreads();

    int r  = tid >> 2;          // 0..63; this thread handles rows r and r+64
    int cg = (tid & 3) << 4;    // 0,16,32,48 (col base)
    float acc[32];
#pragma unroll
    for (int j = 0; j < 32; j++) acc[j] = 0.f;
    const float* y0 = sY + r * 68;
    const float* y1 = sY + (r + 64) * 68;
#pragma unroll
    for (int k = 0; k < 64; k++) {
        float yk0 = y0[k];
        float yk1 = y1[k];
        const float4* wr = (const float4*)(sW + k * 64 + cg);
#pragma unroll
        for (int q = 0; q < 4; q++) {
            float4 w = wr[q];
            acc[q * 4 + 0]      = fmaf(yk0, w.x, acc[q * 4 + 0]);
            acc[q * 4 + 1]      = fmaf(yk0, w.y, acc[q * 4 + 1]);
            acc[q * 4 + 2]      = fmaf(yk0, w.z, acc[q * 4 + 2]);
            acc[q * 4 + 3]      = fmaf(yk0, w.w, acc[q * 4 + 3]);
            acc[16 + q * 4 + 0] = fmaf(yk1, w.x, acc[16 + q * 4 + 0]);
            acc[16 + q * 4 + 1] = fmaf(yk1, w.y, acc[16 + q * 4 + 1]);
            acc[16 + q * 4 + 2] = fmaf(yk1, w.z, acc[16 + q * 4 + 2]);
            acc[16 + q * 4 + 3] = fmaf(yk1, w.w, acc[16 + q * 4 + 3]);
        }
    }
    int grow0 = row0 + r;
    int grow1 = row0 + 64 + r;
#pragma unroll
    for (int j = 0; j < 16; j++) {
        acc[j]      = fmaxf(acc[j]      + sB[cg + j], 0.f);
        acc[16 + j] = fmaxf(acc[16 + j] + sB[cg + j], 0.f);
    }
    if (grow0 < n) {
        float4* o4 = (float4*)(out + grow0 * 64 + cg);
        o4[0] = make_float4(acc[0],  acc[1],  acc[2],  acc[3]);
        o4[1] = make_float4(acc[4],  acc[5],  acc[6],  acc[7]);
        o4[2] = make_float4(acc[8],  acc[9],  acc[10], acc[11]);
        o4[3] = make_float4(acc[12], acc[13], acc[14], acc[15]);
    } else {
#pragma unroll
        for (int j = 0; j < 16; j++) acc[j] = 0.f;
    }
    if (grow1 < n) {
        float4* o4 = (float4*)(out + grow1 * 64 + cg);
        o4[0] = make_float4(acc[16], acc[17], acc[18], acc[19]);
        o4[1] = make_float4(acc[20], acc[21], acc[22], acc[23]);
        o4[2] = make_float4(acc[24], acc[25], acc[26], acc[27]);
        o4[3] = make_float4(acc[28], acc[29], acc[30], acc[31]);
    } else {
#pragma unroll
        for (int j = 0; j < 16; j++) acc[16 + j] = 0.f;
    }
    // BN partial stats: combine both rows, reduce over the 8 r-values in the warp
    float s[16], sq[16];
#pragma unroll
    for (int j = 0; j < 16; j++) {
        s[j]  = acc[j] + acc[16 + j];
        sq[j] = acc[j] * acc[j] + acc[16 + j] * acc[16 + j];
    }
#pragma unroll
    for (int off = 4; off < 32; off <<= 1) {
#pragma unroll
        for (int j = 0; j < 16; j++) {
            s[j]  += __shfl_xor_sync(0xffffffffu, s[j],  off);
            sq[j] += __shfl_xor_sync(0xffffffffu, sq[j], off);
        }
    }
    if (lane < 4) {
#pragma unroll
        for (int j = 0; j < 16; j++) {
            atomicAdd(&sSum[cg + j],      s[j]);
            atomicAdd(&sSum[64 + cg + j], sq[j]);
        }
    }
    __syncthreads();
    if (tid < 128) atomicAdd(&g_stats[tid], sSum[tid]);
}

// ---------------- 6. fused BN stats + apply (in place on out) ----------------
__global__ void k_bn(float4* __restrict__ out,
                     const float* __restrict__ gamma,
                     const float* __restrict__ beta, int n) {
    __shared__ float ssc[64], ssh[64];
    int tid = threadIdx.x;
    if (tid < 64) {
        float inv_n = 1.0f / (float)n;
        float mean = g_stats[tid] * inv_n;
        float var  = fmaxf(g_stats[64 + tid] * inv_n - mean * mean, 0.f);
        float sc = gamma[tid] * rsqrtf(var + 1e-5f);
        ssc[tid] = sc;
        ssh[tid] = beta[tid] - mean * sc;
    }
    __syncthreads();
    int i = blockIdx.x * blockDim.x + tid;
    if (i < n * 16) {
        float4 v  = out[i];
        float4 sc = ((const float4*)ssc)[i & 15];
        float4 sh = ((const float4*)ssh)[i & 15];
        v.x = fmaf(v.x, sc.x, sh.x);
        v.y = fmaf(v.y, sc.y, sh.y);
        v.z = fmaf(v.z, sc.z, sh.z);
        v.w = fmaf(v.w, sc.w, sh.w);
        out[i] = v;
    }
}

extern "C" void kernel_launch(void* const* d_in, const int* in_sizes, int n_in,
                              void* d_out, int out_size) {
    const float* x     = (const float*)d_in[0];
    const int*   ei    = (const int*)d_in[1];
    const float* W     = (const float*)d_in[2];
    const float* b     = (const float*)d_in[3];
    const float* gamma = (const float*)d_in[4];
    const float* beta  = (const float*)d_in[5];
    float* out = (float*)d_out;

    int N = in_sizes[0] / DIM;
    int E = in_sizes[1] / 2;
    const int* src = ei;
    const int* dst = ei + E;

    void* p_deg = nullptr;
    cudaGetSymbolAddress(&p_deg, g_deg);
    cudaMemsetAsync(p_deg, 0, (size_t)N * sizeof(int));

    const int GEMM_SMEM = (4096 + 128 * 68 + 64 + 128) * (int)sizeof(float);
    cudaFuncSetAttribute(k_gemm, cudaFuncAttributeMaxDynamicSharedMemorySize, GEMM_SMEM);

    k_hist<<<(E + 255) / 256, 256>>>(dst, E);
    k_prep<<<1 + (N * 8 + 1023) / 1024, 1024>>>((const float4*)x, N);
    k_fill<<<(E + 255) / 256, 256>>>(src, dst, E);
    k_agg<<<(N + 7) / 8, 256>>>(N);
    k_gemm<<<(N + 127) / 128, 256, GEMM_SMEM>>>(W, b, out, N);
    k_bn<<<(N * 16 + 255) / 256, 256>>>((float4*)out, gamma, beta, N);
}

// round 9
// speedup vs baseline: 1.3618x; 1.0377x over previous
#include <cuda_runtime.h>
#include <cuda_fp16.h>

#define MAXN 100000
#define MAXE 1000000
#define DIM 64

// ---------------- scratch (device globals; no allocation allowed) ----------------
__device__ int     g_deg[MAXN];        // edge count per dst (memset 0; deg = count+1)
__device__ float   g_dinv[MAXN];
__device__ int     g_off[MAXN + 1];
__device__ int     g_cur[MAXN];
__device__ int     g_srcs[MAXE];
__device__ __half2 g_xsh[MAXN * 32];   // fp16 dinv[i]*x[i], 32 half2 per node
__device__ float   g_y[MAXN * DIM];    // aggregated features (fp32)
__device__ float   g_stats[2 * DIM];   // [0:64) col sums, [64:128) col sumsq

// ---------------- 1. degree histogram over dst ----------------
__global__ void k_hist(const int* __restrict__ dst, int E) {
    int e = blockIdx.x * blockDim.x + threadIdx.x;
    if (e < E) atomicAdd(&g_deg[dst[e]], 1);
}

// ---------------- 2. combined: block 0 = scan, blocks 1.. = xs ----------------
__global__ void __launch_bounds__(1024) k_prep(const float4* __restrict__ x4, int n) {
    int tid = threadIdx.x, lane = tid & 31, wid = tid >> 5;
    if (blockIdx.x != 0) {
        // ---- xs = fp16(dinv * x), 8 floats / thread; emits g_dinv ----
        int i = (blockIdx.x - 1) * 1024 + tid;
        if (i < n * 8) {
            int node = i >> 3;
            float dv = rsqrtf((float)(g_deg[node] + 1));  // +1 self loop
            float4 a = x4[2 * i], c = x4[2 * i + 1];
            __half2 h[4];
            h[0] = __floats2half2_rn(a.x * dv, a.y * dv);
            h[1] = __floats2half2_rn(a.z * dv, a.w * dv);
            h[2] = __floats2half2_rn(c.x * dv, c.y * dv);
            h[3] = __floats2half2_rn(c.z * dv, c.w * dv);
            *(uint4*)&g_xsh[i * 4] = *(uint4*)h;          // one 16B store
            if ((i & 7) == 0) g_dinv[node] = dv;
        }
        return;
    }
    // ---- exclusive scan of edge counts -> offsets (warp-shfl) ----
    __shared__ int warppre[32];
    __shared__ int s_run, s_tot;
    if (tid == 0) s_run = 0;
    if (tid < 128) g_stats[tid] = 0.f;     // fold stats zeroing in here
    __syncthreads();
    int nchunk = (n + 4095) >> 12;
    for (int c = 0; c < nchunk; c++) {
        int base = (c << 12) + tid * 4;
        int v0 = (base     < n) ? g_deg[base]     : 0;
        int v1 = (base + 1 < n) ? g_deg[base + 1] : 0;
        int v2 = (base + 2 < n) ? g_deg[base + 2] : 0;
        int v3 = (base + 3 < n) ? g_deg[base + 3] : 0;
        int t = v0 + v1 + v2 + v3;
        int s = t;
#pragma unroll
        for (int o = 1; o < 32; o <<= 1) {
            int u = __shfl_up_sync(0xffffffffu, s, o);
            if (lane >= o) s += u;
        }
        if (lane == 31) warppre[wid] = s;
        __syncthreads();
        if (wid == 0) {
            int w = warppre[lane];
            int ws = w;
#pragma unroll
            for (int o = 1; o < 32; o <<= 1) {
                int u = __shfl_up_sync(0xffffffffu, ws, o);
                if (lane >= o) ws += u;
            }
            warppre[lane] = ws - w;          // exclusive warp prefix
            if (lane == 31) s_tot = ws;      // chunk total
        }
        __syncthreads();
        int excl = s_run + warppre[wid] + (s - t);
        if (base     < n) { g_off[base]     = excl; g_cur[base]     = excl; } excl += v0;
        if (base + 1 < n) { g_off[base + 1] = excl; g_cur[base + 1] = excl; } excl += v1;
        if (base + 2 < n) { g_off[base + 2] = excl; g_cur[base + 2] = excl; } excl += v2;
        if (base + 3 < n) { g_off[base + 3] = excl; g_cur[base + 3] = excl; }
        __syncthreads();
        if (tid == 0) s_run += s_tot;
        __syncthreads();
    }
    if (tid == 0) g_off[n] = s_run;
}

// ---------------- 3. CSR fill ----------------
__global__ void k_fill(const int* __restrict__ src, const int* __restrict__ dst, int E) {
    int e = blockIdx.x * blockDim.x + threadIdx.x;
    if (e < E) {
        int d = dst[e];
        int p = atomicAdd(&g_cur[d], 1);
        g_srcs[p] = src[e];
    }
}

// ---------------- 4. aggregation: one warp per node, 2 edges per warp-load -------
// Half-warp h handles even/odd edge of each pair; lane loads 8B (4 halves).
// 8-edge windows are summed with HADD2 (fp16), then folded into fp32 accumulators:
// ~22 issued instr per 8 edges per lane vs ~60 for all-fp32.
__global__ void __launch_bounds__(256) k_agg(int n) {
    int warp = (blockIdx.x * blockDim.x + threadIdx.x) >> 5;
    int lane = threadIdx.x & 31;
    if (warp >= n) return;
    int h  = lane >> 4;        // 0 = even edge of pair, 1 = odd edge
    int sl = lane & 15;        // uint2 column index within row
    const uint2* xs = (const uint2*)g_xsh;   // 16 uint2 per node row (128B)

    int s0 = g_off[warp], s1 = g_off[warp + 1];
    float4 a = make_float4(0.f, 0.f, 0.f, 0.f);
    if (h == 0) {              // self-loop term once
        uint2 sv = xs[warp * 16 + sl];
        float2 lo = __half22float2(*(__half2*)&sv.x);
        float2 hi = __half22float2(*(__half2*)&sv.y);
        a = make_float4(lo.x, lo.y, hi.x, hi.y);
    }
    int e = s0;
    for (; e + 8 <= s1; e += 8) {
        int i0 = g_srcs[e + 0 + h];
        int i1 = g_srcs[e + 2 + h];
        int i2 = g_srcs[e + 4 + h];
        int i3 = g_srcs[e + 6 + h];
        uint2 v0 = xs[i0 * 16 + sl];
        uint2 v1 = xs[i1 * 16 + sl];
        uint2 v2 = xs[i2 * 16 + sl];
        uint2 v3 = xs[i3 * 16 + sl];
        // fp16 window sum (3 HADD2 per component pair), then fp32 fold
        __half2 wlo = __hadd2(__hadd2(*(__half2*)&v0.x, *(__half2*)&v1.x),
                              __hadd2(*(__half2*)&v2.x, *(__half2*)&v3.x));
        __half2 whi = __hadd2(__hadd2(*(__half2*)&v0.y, *(__half2*)&v1.y),
                              __hadd2(*(__half2*)&v2.y, *(__half2*)&v3.y));
        float2 flo = __half22float2(wlo);
        float2 fhi = __half22float2(whi);
        a.x += flo.x; a.y += flo.y; a.z += fhi.x; a.w += fhi.y;
    }
    for (; e + 2 <= s1; e += 2) {           // leftover pairs (fp32 fold directly)
        int i0 = g_srcs[e + h];
        uint2 v = xs[i0 * 16 + sl];
        float2 lo = __half22float2(*(__half2*)&v.x);
        float2 hi = __half22float2(*(__half2*)&v.y);
        a.x += lo.x; a.y += lo.y; a.z += hi.x; a.w += hi.y;
    }
    if (e < s1 && h == 0) {                 // odd single edge
        uint2 v = xs[g_srcs[e] * 16 + sl];
        float2 lo = __half22float2(*(__half2*)&v.x);
        float2 hi = __half22float2(*(__half2*)&v.y);
        a.x += lo.x; a.y += lo.y; a.z += hi.x; a.w += hi.y;
    }
    // merge odd-edge half-warp into even-edge half-warp
    a.x += __shfl_xor_sync(0xffffffffu, a.x, 16);
    a.y += __shfl_xor_sync(0xffffffffu, a.y, 16);
    a.z += __shfl_xor_sync(0xffffffffu, a.z, 16);
    a.w += __shfl_xor_sync(0xffffffffu, a.w, 16);
    if (h == 0) {
        float dv = g_dinv[warp];
        a.x *= dv; a.y *= dv; a.z *= dv; a.w *= dv;
        ((float4*)(g_y + warp * 64))[sl] = a;
    }
}

// ---------------- 5. GEMM 128-row tile (y @ W + b), ReLU, store, BN stats -------
__global__ void __launch_bounds__(256) k_gemm(const float* __restrict__ W,
                                              const float* __restrict__ b,
                                              float* __restrict__ out, int n) {
    extern __shared__ float smem[];
    float* sW   = smem;                 // 4096
    float* sY   = smem + 4096;          // 128*68 = 8704
    float* sB   = sY + 128 * 68;        // 64
    float* sSum = sB + 64;              // 128
    int tid = threadIdx.x, lane = tid & 31;

    for (int i = tid; i < 4096; i += 256) sW[i] = W[i];
    if (tid < 64) sB[tid] = b[tid];
    if (tid < 128) sSum[tid] = 0.f;

    int row0 = blockIdx.x * 128;
    const float4* y4 = (const float4*)g_y;
    for (int i = tid; i < 128 * 16; i += 256) {
        int r = i >> 4, q = i & 15;
        int grow = row0 + r;
        float4 v = (grow < n) ? y4[grow * 16 + q] : make_float4(0.f, 0.f, 0.f, 0.f);
        ((float4*)(sY + r * 68))[q] = v;
    }
    __syncthreads();

    int r  = tid >> 2;          // 0..63; this thread handles rows r and r+64
    int cg = (tid & 3) << 4;    // 0,16,32,48 (col base)
    float acc[32];
#pragma unroll
    for (int j = 0; j < 32; j++) acc[j] = 0.f;
    const float* y0 = sY + r * 68;
    const float* y1 = sY + (r + 64) * 68;
#pragma unroll
    for (int k = 0; k < 64; k++) {
        float yk0 = y0[k];
        float yk1 = y1[k];
        const float4* wr = (const float4*)(sW + k * 64 + cg);
#pragma unroll
        for (int q = 0; q < 4; q++) {
            float4 w = wr[q];
            acc[q * 4 + 0]      = fmaf(yk0, w.x, acc[q * 4 + 0]);
            acc[q * 4 + 1]      = fmaf(yk0, w.y, acc[q * 4 + 1]);
            acc[q * 4 + 2]      = fmaf(yk0, w.z, acc[q * 4 + 2]);
            acc[q * 4 + 3]      = fmaf(yk0, w.w, acc[q * 4 + 3]);
            acc[16 + q * 4 + 0] = fmaf(yk1, w.x, acc[16 + q * 4 + 0]);
            acc[16 + q * 4 + 1] = fmaf(yk1, w.y, acc[16 + q * 4 + 1]);
            acc[16 + q * 4 + 2] = fmaf(yk1, w.z, acc[16 + q * 4 + 2]);
            acc[16 + q * 4 + 3] = fmaf(yk1, w.w, acc[16 + q * 4 + 3]);
        }
    }
    int grow0 = row0 + r;
    int grow1 = row0 + 64 + r;
#pragma unroll
    for (int j = 0; j < 16; j++) {
        acc[j]      = fmaxf(acc[j]      + sB[cg + j], 0.f);
        acc[16 + j] = fmaxf(acc[16 + j] + sB[cg + j], 0.f);
    }
    if (grow0 < n) {
        float4* o4 = (float4*)(out + grow0 * 64 + cg);
        o4[0] = make_float4(acc[0],  acc[1],  acc[2],  acc[3]);
        o4[1] = make_float4(acc[4],  acc[5],  acc[6],  acc[7]);
        o4[2] = make_float4(acc[8],  acc[9],  acc[10], acc[11]);
        o4[3] = make_float4(acc[12], acc[13], acc[14], acc[15]);
    } else {
#pragma unroll
        for (int j = 0; j < 16; j++) acc[j] = 0.f;
    }
    if (grow1 < n) {
        float4* o4 = (float4*)(out + grow1 * 64 + cg);
        o4[0] = make_float4(acc[16], acc[17], acc[18], acc[19]);
        o4[1] = make_float4(acc[20], acc[21], acc[22], acc[23]);
        o4[2] = make_float4(acc[24], acc[25], acc[26], acc[27]);
        o4[3] = make_float4(acc[28], acc[29], acc[30], acc[31]);
    } else {
#pragma unroll
        for (int j = 0; j < 16; j++) acc[16 + j] = 0.f;
    }
    // BN partial stats: combine both rows, reduce over the 8 r-values in the warp
    float s[16], sq[16];
#pragma unroll
    for (int j = 0; j < 16; j++) {
        s[j]  = acc[j] + acc[16 + j];
        sq[j] = acc[j] * acc[j] + acc[16 + j] * acc[16 + j];
    }
#pragma unroll
    for (int off = 4; off < 32; off <<= 1) {
#pragma unroll
        for (int j = 0; j < 16; j++) {
            s[j]  += __shfl_xor_sync(0xffffffffu, s[j],  off);
            sq[j] += __shfl_xor_sync(0xffffffffu, sq[j], off);
        }
    }
    if (lane < 4) {
#pragma unroll
        for (int j = 0; j < 16; j++) {
            atomicAdd(&sSum[cg + j],      s[j]);
            atomicAdd(&sSum[64 + cg + j], sq[j]);
        }
    }
    __syncthreads();
    if (tid < 128) atomicAdd(&g_stats[tid], sSum[tid]);
}

// ---------------- 6. fused BN stats + apply (in place on out) ----------------
__global__ void k_bn(float4* __restrict__ out,
                     const float* __restrict__ gamma,
                     const float* __restrict__ beta, int n) {
    __shared__ float ssc[64], ssh[64];
    int tid = threadIdx.x;
    if (tid < 64) {
        float inv_n = 1.0f / (float)n;
        float mean = g_stats[tid] * inv_n;
        float var  = fmaxf(g_stats[64 + tid] * inv_n - mean * mean, 0.f);
        float sc = gamma[tid] * rsqrtf(var + 1e-5f);
        ssc[tid] = sc;
        ssh[tid] = beta[tid] - mean * sc;
    }
    __syncthreads();
    int i = blockIdx.x * blockDim.x + tid;
    if (i < n * 16) {
        float4 v  = out[i];
        float4 sc = ((const float4*)ssc)[i & 15];
        float4 sh = ((const float4*)ssh)[i & 15];
        v.x = fmaf(v.x, sc.x, sh.x);
        v.y = fmaf(v.y, sc.y, sh.y);
        v.z = fmaf(v.z, sc.z, sh.z);
        v.w = fmaf(v.w, sc.w, sh.w);
        out[i] = v;
    }
}

extern "C" void kernel_launch(void* const* d_in, const int* in_sizes, int n_in,
                              void* d_out, int out_size) {
    const float* x     = (const float*)d_in[0];
    const int*   ei    = (const int*)d_in[1];
    const float* W     = (const float*)d_in[2];
    const float* b     = (const float*)d_in[3];
    const float* gamma = (const float*)d_in[4];
    const float* beta  = (const float*)d_in[5];
    float* out = (float*)d_out;

    int N = in_sizes[0] / DIM;
    int E = in_sizes[1] / 2;
    const int* src = ei;
    const int* dst = ei + E;

    void* p_deg = nullptr;
    cudaGetSymbolAddress(&p_deg, g_deg);
    cudaMemsetAsync(p_deg, 0, (size_t)N * sizeof(int));

    const int GEMM_SMEM = (4096 + 128 * 68 + 64 + 128) * (int)sizeof(float);
    cudaFuncSetAttribute(k_gemm, cudaFuncAttributeMaxDynamicSharedMemorySize, GEMM_SMEM);

    k_hist<<<(E + 255) / 256, 256>>>(dst, E);
    k_prep<<<1 + (N * 8 + 1023) / 1024, 1024>>>((const float4*)x, N);
    k_fill<<<(E + 255) / 256, 256>>>(src, dst, E);
    k_agg<<<(N + 7) / 8, 256>>>(N);
    k_gemm<<<(N + 127) / 128, 256, GEMM_SMEM>>>(W, b, out, N);
    k_bn<<<(N * 16 + 255) / 256, 256>>>((float4*)out, gamma, beta, N);
}

// round 11
// speedup vs baseline: 1.5694x; 1.1524x over previous
#include <cuda_runtime.h>
#include <cuda_fp16.h>

#define MAXN 100000
#define MAXE 1000000
#define DIM 64

// ---------------- scratch (device globals; no allocation allowed) ----------------
__device__ int     g_deg[MAXN];        // edge count per dst (memset 0; deg = count+1)
__device__ float   g_dinv[MAXN];
__device__ int     g_off[MAXN + 1];
__device__ int     g_cur[MAXN];
__device__ int     g_srcs[MAXE];
__device__ __half2 g_xsh[MAXN * 32];   // fp16 dinv[i]*x[i], 32 half2 per node
__device__ __half2 g_yh[MAXN * 32];    // fp16 aggregated features, 32 half2 per node
__device__ float   g_stats[2 * DIM];   // [0:64) col sums, [64:128) col sumsq

// ---- packed f32x2 helpers (sm_103a FFMA2 path) ----
__device__ __forceinline__ unsigned long long pack_dup(float a) {
    unsigned long long r;
    asm("mov.b64 %0, {%1, %1};" : "=l"(r) : "f"(a));
    return r;
}
__device__ __forceinline__ void ffma2(unsigned long long& d, unsigned long long a, unsigned long long b) {
    asm("fma.rn.f32x2 %0, %1, %2, %0;" : "+l"(d) : "l"(a), "l"(b));
}
__device__ __forceinline__ float2 unpack2(unsigned long long v) {
    float2 f;
    asm("mov.b64 {%0, %1}, %2;" : "=f"(f.x), "=f"(f.y) : "l"(v));
    return f;
}

// ---------------- 1. degree histogram over dst ----------------
__global__ void k_hist(const int* __restrict__ dst, int E) {
    int e = blockIdx.x * blockDim.x + threadIdx.x;
    if (e < E) atomicAdd(&g_deg[dst[e]], 1);
}

// ---------------- 2. combined: block 0 = scan, blocks 1.. = xs ----------------
__global__ void __launch_bounds__(1024) k_prep(const float4* __restrict__ x4, int n) {
    int tid = threadIdx.x, lane = tid & 31, wid = tid >> 5;
    if (blockIdx.x != 0) {
        // ---- xs = fp16(dinv * x), 8 floats / thread; emits g_dinv ----
        int i = (blockIdx.x - 1) * 1024 + tid;
        if (i < n * 8) {
            int node = i >> 3;
            float dv = rsqrtf((float)(g_deg[node] + 1));  // +1 self loop
            float4 a = x4[2 * i], c = x4[2 * i + 1];
            __half2 h[4];
            h[0] = __floats2half2_rn(a.x * dv, a.y * dv);
            h[1] = __floats2half2_rn(a.z * dv, a.w * dv);
            h[2] = __floats2half2_rn(c.x * dv, c.y * dv);
            h[3] = __floats2half2_rn(c.z * dv, c.w * dv);
            *(uint4*)&g_xsh[i * 4] = *(uint4*)h;          // one 16B store
            if ((i & 7) == 0) g_dinv[node] = dv;
        }
        return;
    }
    // ---- exclusive scan of edge counts -> offsets (warp-shfl) ----
    __shared__ int warppre[32];
    __shared__ int s_run, s_tot;
    if (tid == 0) s_run = 0;
    if (tid < 128) g_stats[tid] = 0.f;     // fold stats zeroing in here
    __syncthreads();
    int nchunk = (n + 4095) >> 12;
    for (int c = 0; c < nchunk; c++) {
        int base = (c << 12) + tid * 4;
        int v0 = (base     < n) ? g_deg[base]     : 0;
        int v1 = (base + 1 < n) ? g_deg[base + 1] : 0;
        int v2 = (base + 2 < n) ? g_deg[base + 2] : 0;
        int v3 = (base + 3 < n) ? g_deg[base + 3] : 0;
        int t = v0 + v1 + v2 + v3;
        int s = t;
#pragma unroll
        for (int o = 1; o < 32; o <<= 1) {
            int u = __shfl_up_sync(0xffffffffu, s, o);
            if (lane >= o) s += u;
        }
        if (lane == 31) warppre[wid] = s;
        __syncthreads();
        if (wid == 0) {
            int w = warppre[lane];
            int ws = w;
#pragma unroll
            for (int o = 1; o < 32; o <<= 1) {
                int u = __shfl_up_sync(0xffffffffu, ws, o);
                if (lane >= o) ws += u;
            }
            warppre[lane] = ws - w;          // exclusive warp prefix
            if (lane == 31) s_tot = ws;      // chunk total
        }
        __syncthreads();
        int excl = s_run + warppre[wid] + (s - t);
        if (base     < n) { g_off[base]     = excl; g_cur[base]     = excl; } excl += v0;
        if (base + 1 < n) { g_off[base + 1] = excl; g_cur[base + 1] = excl; } excl += v1;
        if (base + 2 < n) { g_off[base + 2] = excl; g_cur[base + 2] = excl; } excl += v2;
        if (base + 3 < n) { g_off[base + 3] = excl; g_cur[base + 3] = excl; }
        __syncthreads();
        if (tid == 0) s_run += s_tot;
        __syncthreads();
    }
    if (tid == 0) g_off[n] = s_run;
}

// ---------------- 3. CSR fill ----------------
__global__ void k_fill(const int* __restrict__ src, const int* __restrict__ dst, int E) {
    int e = blockIdx.x * blockDim.x + threadIdx.x;
    if (e < E) {
        int d = dst[e];
        int p = atomicAdd(&g_cur[d], 1);
        g_srcs[p] = src[e];
    }
}

// ---------------- 4. aggregation: one warp per node, 2 edges per warp-load -------
__global__ void __launch_bounds__(256) k_agg(int n) {
    int warp = (blockIdx.x * blockDim.x + threadIdx.x) >> 5;
    int lane = threadIdx.x & 31;
    if (warp >= n) return;
    int h  = lane >> 4;        // 0 = even edge of pair, 1 = odd edge
    int sl = lane & 15;        // uint2 column index within row
    const uint2* xs = (const uint2*)g_xsh;   // 16 uint2 per node row (128B)

    int s0 = g_off[warp], s1 = g_off[warp + 1];
    float4 a = make_float4(0.f, 0.f, 0.f, 0.f);
    if (h == 0) {              // self-loop term once
        uint2 sv = xs[warp * 16 + sl];
        float2 lo = __half22float2(*(__half2*)&sv.x);
        float2 hi = __half22float2(*(__half2*)&sv.y);
        a = make_float4(lo.x, lo.y, hi.x, hi.y);
    }
    int e = s0;
    for (; e + 8 <= s1; e += 8) {
        int i0 = g_srcs[e + 0 + h];
        int i1 = g_srcs[e + 2 + h];
        int i2 = g_srcs[e + 4 + h];
        int i3 = g_srcs[e + 6 + h];
        uint2 v0 = xs[i0 * 16 + sl];
        uint2 v1 = xs[i1 * 16 + sl];
        uint2 v2 = xs[i2 * 16 + sl];
        uint2 v3 = xs[i3 * 16 + sl];
        // fp16 window sum (HADD2), then fp32 fold
        __half2 wlo = __hadd2(__hadd2(*(__half2*)&v0.x, *(__half2*)&v1.x),
                              __hadd2(*(__half2*)&v2.x, *(__half2*)&v3.x));
        __half2 whi = __hadd2(__hadd2(*(__half2*)&v0.y, *(__half2*)&v1.y),
                              __hadd2(*(__half2*)&v2.y, *(__half2*)&v3.y));
        float2 flo = __half22float2(wlo);
        float2 fhi = __half22float2(whi);
        a.x += flo.x; a.y += flo.y; a.z += fhi.x; a.w += fhi.y;
    }
    for (; e + 2 <= s1; e += 2) {           // leftover pairs (fp32 fold directly)
        int i0 = g_srcs[e + h];
        uint2 v = xs[i0 * 16 + sl];
        float2 lo = __half22float2(*(__half2*)&v.x);
        float2 hi = __half22float2(*(__half2*)&v.y);
        a.x += lo.x; a.y += lo.y; a.z += hi.x; a.w += hi.y;
    }
    if (e < s1 && h == 0) {                 // odd single edge
        uint2 v = xs[g_srcs[e] * 16 + sl];
        float2 lo = __half22float2(*(__half2*)&v.x);
        float2 hi = __half22float2(*(__half2*)&v.y);
        a.x += lo.x; a.y += lo.y; a.z += hi.x; a.w += hi.y;
    }
    // merge odd-edge half-warp into even-edge half-warp
    a.x += __shfl_xor_sync(0xffffffffu, a.x, 16);
    a.y += __shfl_xor_sync(0xffffffffu, a.y, 16);
    a.z += __shfl_xor_sync(0xffffffffu, a.z, 16);
    a.w += __shfl_xor_sync(0xffffffffu, a.w, 16);
    if (h == 0) {
        float dv = g_dinv[warp];
        a.x *= dv; a.y *= dv; a.z *= dv; a.w *= dv;
        uint2 o;
        *(__half2*)&o.x = __floats2half2_rn(a.x, a.y);
        *(__half2*)&o.y = __floats2half2_rn(a.z, a.w);
        ((uint2*)g_yh)[warp * 16 + sl] = o;
    }
}

// ---------------- 5. GEMM 256-row tile, f32x2 FMA, 4 rows/thread ----------------
__global__ void __launch_bounds__(256) k_gemm(const float* __restrict__ W,
                                              const float* __restrict__ b,
                                              float* __restrict__ out, int n) {
    extern __shared__ float smem[];
    float* sW   = smem;                 // 4096
    float* sY   = smem + 4096;          // 256*68
    float* sB   = sY + 256 * 68;        // 64
    float* sSum = sB + 64;              // 128
    int tid = threadIdx.x, lane = tid & 31;

    for (int i = tid; i < 4096; i += 256) sW[i] = W[i];
    if (tid < 64) sB[tid] = b[tid];
    if (tid < 128) sSum[tid] = 0.f;

    int row0 = blockIdx.x * 256;
    const uint4* y4 = (const uint4*)g_yh;   // 8 uint4 (16B) per node row
    for (int i = tid; i < 256 * 8; i += 256) {
        int r = i >> 3, q = i & 7;
        int grow = row0 + r;
        float4 lo = make_float4(0.f, 0.f, 0.f, 0.f), hi = lo;
        if (grow < n) {
            uint4 v = y4[grow * 8 + q];
            float2 f0 = __half22float2(*(__half2*)&v.x);
            float2 f1 = __half22float2(*(__half2*)&v.y);
            float2 f2 = __half22float2(*(__half2*)&v.z);
            float2 f3 = __half22float2(*(__half2*)&v.w);
            lo = make_float4(f0.x, f0.y, f1.x, f1.y);
            hi = make_float4(f2.x, f2.y, f3.x, f3.y);
        }
        ((float4*)(sY + r * 68))[q * 2]     = lo;
        ((float4*)(sY + r * 68))[q * 2 + 1] = hi;
    }
    __syncthreads();

    int r  = tid >> 2;          // 0..63; rows r, r+64, r+128, r+192
    int cg = (tid & 3) << 4;    // 0,16,32,48 (col base)
    unsigned long long acc2[32];  // [m*8 + p]: row m, col pair p (cols cg+2p, cg+2p+1)
#pragma unroll
    for (int j = 0; j < 32; j++) acc2[j] = 0ull;
    const float* y0 = sY + r * 68;
    const float* y1 = sY + (r + 64) * 68;
    const float* y2 = sY + (r + 128) * 68;
    const float* y3 = sY + (r + 192) * 68;
#pragma unroll
    for (int k = 0; k < 64; k++) {
        unsigned long long yp0 = pack_dup(y0[k]);
        unsigned long long yp1 = pack_dup(y1[k]);
        unsigned long long yp2 = pack_dup(y2[k]);
        unsigned long long yp3 = pack_dup(y3[k]);
        const unsigned long long* wp = (const unsigned long long*)(sW + k * 64 + cg);
#pragma unroll
        for (int p = 0; p < 8; p++) {
            unsigned long long w = wp[p];
            ffma2(acc2[p],      yp0, w);
            ffma2(acc2[8 + p],  yp1, w);
            ffma2(acc2[16 + p], yp2, w);
            ffma2(acc2[24 + p], yp3, w);
        }
    }
    // epilogue per row: bias + ReLU + store + stats partials
    float s[16], sq[16];
#pragma unroll
    for (int j = 0; j < 16; j++) { s[j] = 0.f; sq[j] = 0.f; }
#pragma unroll
    for (int m = 0; m < 4; m++) {
        int grow = row0 + m * 64 + r;
        float f[16];
#pragma unroll
        for (int p = 0; p < 8; p++) {
            float2 v = unpack2(acc2[m * 8 + p]);
            f[p * 2]     = v.x;
            f[p * 2 + 1] = v.y;
        }
#pragma unroll
        for (int j = 0; j < 16; j++) f[j] = fmaxf(f[j] + sB[cg + j], 0.f);
        if (grow < n) {
            float4* o4 = (float4*)(out + grow * 64 + cg);
            o4[0] = make_float4(f[0],  f[1],  f[2],  f[3]);
            o4[1] = make_float4(f[4],  f[5],  f[6],  f[7]);
            o4[2] = make_float4(f[8],  f[9],  f[10], f[11]);
            o4[3] = make_float4(f[12], f[13], f[14], f[15]);
        } else {
#pragma unroll
            for (int j = 0; j < 16; j++) f[j] = 0.f;   // don't pollute stats
        }
#pragma unroll
        for (int j = 0; j < 16; j++) {
            s[j]  += f[j];
            sq[j] += f[j] * f[j];
        }
    }
    // reduce over the 8 r-values in the warp (lanes differing in bits 2..4)
#pragma unroll
    for (int off = 4; off < 32; off <<= 1) {
#pragma unroll
        for (int j = 0; j < 16; j++) {
            s[j]  += __shfl_xor_sync(0xffffffffu, s[j],  off);
            sq[j] += __shfl_xor_sync(0xffffffffu, sq[j], off);
        }
    }
    if (lane < 4) {
#pragma unroll
        for (int j = 0; j < 16; j++) {
            atomicAdd(&sSum[cg + j],      s[j]);
            atomicAdd(&sSum[64 + cg + j], sq[j]);
        }
    }
    __syncthreads();
    if (tid < 128) atomicAdd(&g_stats[tid], sSum[tid]);
}

// ---------------- 6. fused BN stats + apply (in place on out) ----------------
__global__ void k_bn(float4* __restrict__ out,
                     const float* __restrict__ gamma,
                     const float* __restrict__ beta, int n) {
    __shared__ float ssc[64], ssh[64];
    int tid = threadIdx.x;
    if (tid < 64) {
        float inv_n = 1.0f / (float)n;
        float mean = g_stats[tid] * inv_n;
        float var  = fmaxf(g_stats[64 + tid] * inv_n - mean * mean, 0.f);
        float sc = gamma[tid] * rsqrtf(var + 1e-5f);
        ssc[tid] = sc;
        ssh[tid] = beta[tid] - mean * sc;
    }
    __syncthreads();
    int i = blockIdx.x * blockDim.x + tid;
    if (i < n * 16) {
        float4 v  = out[i];
        float4 sc = ((const float4*)ssc)[i & 15];
        float4 sh = ((const float4*)ssh)[i & 15];
        v.x = fmaf(v.x, sc.x, sh.x);
        v.y = fmaf(v.y, sc.y, sh.y);
        v.z = fmaf(v.z, sc.z, sh.z);
        v.w = fmaf(v.w, sc.w, sh.w);
        out[i] = v;
    }
}

extern "C" void kernel_launch(void* const* d_in, const int* in_sizes, int n_in,
                              void* d_out, int out_size) {
    const float* x     = (const float*)d_in[0];
    const int*   ei    = (const int*)d_in[1];
    const float* W     = (const float*)d_in[2];
    const float* b     = (const float*)d_in[3];
    const float* gamma = (const float*)d_in[4];
    const float* beta  = (const float*)d_in[5];
    float* out = (float*)d_out;

    int N = in_sizes[0] / DIM;
    int E = in_sizes[1] / 2;
    const int* src = ei;
    const int* dst = ei + E;

    void* p_deg = nullptr;
    cudaGetSymbolAddress(&p_deg, g_deg);
    cudaMemsetAsync(p_deg, 0, (size_t)N * sizeof(int));

    const int GEMM_SMEM = (4096 + 256 * 68 + 64 + 128) * (int)sizeof(float);
    cudaFuncSetAttribute(k_gemm, cudaFuncAttributeMaxDynamicSharedMemorySize, GEMM_SMEM);

    k_hist<<<(E + 255) / 256, 256>>>(dst, E);
    k_prep<<<1 + (N * 8 + 1023) / 1024, 1024>>>((const float4*)x, N);
    k_fill<<<(E + 255) / 256, 256>>>(src, dst, E);
    k_agg<<<(N + 7) / 8, 256>>>(N);
    k_gemm<<<(N + 255) / 256, 256, GEMM_SMEM>>>(W, b, out, N);
    k_bn<<<(N * 16 + 255) / 256, 256>>>((float4*)out, gamma, beta, N);
}